// round 3
// baseline (speedup 1.0000x reference)
#include <cuda_runtime.h>
#include <cstdint>

#define DM   1024
#define NH   16
#define DKH  64
#define BB   4
#define TS   2048
#define MTOT (BB*TS)        // 8192
#define ELEMS (MTOT*DM)     // 8388608

// Scratch (static device memory — no allocation allowed)
__device__ float g_q[ELEMS];
__device__ float g_k[ELEMS];
__device__ float g_v[ELEMS];
__device__ float g_y[ELEMS];

__device__ __forceinline__ float tfr(float f) {
    unsigned u;
    asm("cvt.rna.tf32.f32 %0, %1;" : "=r"(u) : "f"(f));
    return __uint_as_float(u);
}

__device__ __forceinline__ void mma8(float* d, const unsigned* a, const unsigned* b) {
    asm volatile(
        "mma.sync.aligned.m16n8k8.row.col.f32.tf32.tf32.f32 "
        "{%0,%1,%2,%3}, {%4,%5,%6,%7}, {%8,%9}, {%0,%1,%2,%3};\n"
        : "+f"(d[0]), "+f"(d[1]), "+f"(d[2]), "+f"(d[3])
        : "r"(a[0]), "r"(a[1]), "r"(a[2]), "r"(a[3]), "r"(b[0]), "r"(b[1]));
}

// ---------------------------------------------------------------------------
// C[M,N] = A[M,K] @ B[N,K]^T + bias.  MODE 0: plain row-major write.
// MODE 1: scatter into q/k/v [B,H,T,64] layouts, Q scaled by 1/sqrt(dk).
// BM=BN=128, BK=16, 256 threads (8 warps, warp tile 64x32).
// ---------------------------------------------------------------------------
template <int MODE>
__global__ void __launch_bounds__(256) gemm_tn(
    const float* __restrict__ A, const float* __restrict__ Bm,
    const float* __restrict__ bias, float* __restrict__ C,
    float* __restrict__ qb, float* __restrict__ kb, float* __restrict__ vb,
    int M, int N, int K)
{
    __shared__ float As[128][20];
    __shared__ float Bs[128][20];

    const int tid  = threadIdx.x;
    const int lane = tid & 31;
    const int warp = tid >> 5;
    const int wm = warp >> 2;     // 0..1
    const int wn = warp & 3;      // 0..3
    const int bm = blockIdx.y * 128;
    const int bn = blockIdx.x * 128;

    float acc[4][4][4];
#pragma unroll
    for (int mi = 0; mi < 4; mi++)
#pragma unroll
        for (int ni = 0; ni < 4; ni++)
#pragma unroll
            for (int q = 0; q < 4; q++) acc[mi][ni][q] = 0.0f;

    const int lr = tid >> 2;        // 0..63
    const int lc = (tid & 3) * 4;   // 0,4,8,12

    for (int kt = 0; kt < K; kt += 16) {
#pragma unroll
        for (int i = 0; i < 2; i++) {
            int r = lr + i * 64;
            float4 av = *(const float4*)(A + (size_t)(bm + r) * K + kt + lc);
            As[r][lc + 0] = tfr(av.x); As[r][lc + 1] = tfr(av.y);
            As[r][lc + 2] = tfr(av.z); As[r][lc + 3] = tfr(av.w);
            float4 bv = *(const float4*)(Bm + (size_t)(bn + r) * K + kt + lc);
            Bs[r][lc + 0] = tfr(bv.x); Bs[r][lc + 1] = tfr(bv.y);
            Bs[r][lc + 2] = tfr(bv.z); Bs[r][lc + 3] = tfr(bv.w);
        }
        __syncthreads();

#pragma unroll
        for (int kk = 0; kk < 16; kk += 8) {
            unsigned a[4][4], b[4][2];
#pragma unroll
            for (int mi = 0; mi < 4; mi++) {
                int r = wm * 64 + mi * 16 + (lane >> 2);
                int c = kk + (lane & 3);
                a[mi][0] = __float_as_uint(As[r][c]);
                a[mi][1] = __float_as_uint(As[r + 8][c]);
                a[mi][2] = __float_as_uint(As[r][c + 4]);
                a[mi][3] = __float_as_uint(As[r + 8][c + 4]);
            }
#pragma unroll
            for (int ni = 0; ni < 4; ni++) {
                int rB = wn * 32 + ni * 8 + (lane >> 2);
                int c  = kk + (lane & 3);
                b[ni][0] = __float_as_uint(Bs[rB][c]);
                b[ni][1] = __float_as_uint(Bs[rB][c + 4]);
            }
#pragma unroll
            for (int mi = 0; mi < 4; mi++)
#pragma unroll
                for (int ni = 0; ni < 4; ni++)
                    mma8(acc[mi][ni], a[mi], b[ni]);
        }
        __syncthreads();
    }

    // Epilogue
#pragma unroll
    for (int mi = 0; mi < 4; mi++) {
#pragma unroll
        for (int ni = 0; ni < 4; ni++) {
            int row = bm + wm * 64 + mi * 16 + (lane >> 2);
            int col = bn + wn * 32 + ni * 8 + 2 * (lane & 3);
#pragma unroll
            for (int half = 0; half < 2; half++) {
                int r = row + half * 8;
                float v0 = acc[mi][ni][half * 2 + 0] + bias[col];
                float v1 = acc[mi][ni][half * 2 + 1] + bias[col + 1];
                if (MODE == 0) {
                    C[(size_t)r * N + col]     = v0;
                    C[(size_t)r * N + col + 1] = v1;
                } else {
                    int which = col >> 10;          // 0=q,1=k,2=v
                    int cc = col & 1023;
                    int hh = cc >> 6, dd = cc & 63;
                    int bi = r >> 11, tt = r & 2047;
                    if (which == 0) { v0 *= 0.125f; v1 *= 0.125f; }  // 1/sqrt(64)
                    float* dst = (which == 0) ? qb : ((which == 1) ? kb : vb);
                    size_t off = ((((size_t)bi * NH + hh) * TS) + tt) * DKH + dd;
                    dst[off]     = v0;
                    dst[off + 1] = v1;
                }
            }
        }
    }
}

// ---------------------------------------------------------------------------
// Flash attention: block = (q-tile 64, head, batch), 128 threads (4 warps),
// each warp owns 16 query rows. K/V tiles of 64 keys streamed through smem.
// Q/K/S smem stride 76, V stride 72: both mma fragment patterns conflict-free.
// ---------------------------------------------------------------------------
#define QS_STRIDE 76
#define VS_STRIDE 72

__global__ void __launch_bounds__(128) attn_kernel(
    const float* __restrict__ qg, const float* __restrict__ kg,
    const float* __restrict__ vg, float* __restrict__ yg)
{
    extern __shared__ float sm[];
    float* Qs = sm;                       // 64*76
    float* Ks = sm + 64 * QS_STRIDE;      // 64*76
    float* Ss = sm + 2 * 64 * QS_STRIDE;  // 64*76
    float* Vs = sm + 3 * 64 * QS_STRIDE;  // 64*72

    const int tid  = threadIdx.x;
    const int lane = tid & 31;
    const int warp = tid >> 5;
    const int qt = blockIdx.x, h = blockIdx.y, b = blockIdx.z;
    const size_t headbase = (((size_t)b * NH + h) * TS) * DKH;
    const int mb = warp * 16;

    // Load Q tile (already scaled by 1/sqrt(dk) in the QKV epilogue)
    {
        const float* qptr = qg + headbase + (size_t)qt * 64 * DKH;
#pragma unroll
        for (int i = 0; i < 8; i++) {
            int idx = i * 128 + tid;            // 1024 float4s
            int r = idx >> 4, c = (idx & 15) * 4;
            float4 v4 = *(const float4*)(qptr + r * 64 + c);
            Qs[r * QS_STRIDE + c + 0] = tfr(v4.x);
            Qs[r * QS_STRIDE + c + 1] = tfr(v4.y);
            Qs[r * QS_STRIDE + c + 2] = tfr(v4.z);
            Qs[r * QS_STRIDE + c + 3] = tfr(v4.w);
        }
    }

    float accO[8][4];
#pragma unroll
    for (int nf = 0; nf < 8; nf++)
#pragma unroll
        for (int q = 0; q < 4; q++) accO[nf][q] = 0.0f;
    float mrow[2] = {-1e30f, -1e30f};
    float lrow[2] = {0.0f, 0.0f};

    for (int j = 0; j < TS / 64; j++) {
        __syncthreads();  // prev-iter K/V readers done (no-op cost on j=0)
        const float* kp = kg + headbase + (size_t)j * 64 * DKH;
        const float* vp = vg + headbase + (size_t)j * 64 * DKH;
#pragma unroll
        for (int i = 0; i < 8; i++) {
            int idx = i * 128 + tid;
            int r = idx >> 4, c = (idx & 15) * 4;
            float4 k4 = *(const float4*)(kp + r * 64 + c);
            Ks[r * QS_STRIDE + c + 0] = tfr(k4.x);
            Ks[r * QS_STRIDE + c + 1] = tfr(k4.y);
            Ks[r * QS_STRIDE + c + 2] = tfr(k4.z);
            Ks[r * QS_STRIDE + c + 3] = tfr(k4.w);
            float4 v4 = *(const float4*)(vp + r * 64 + c);
            Vs[r * VS_STRIDE + c + 0] = tfr(v4.x);
            Vs[r * VS_STRIDE + c + 1] = tfr(v4.y);
            Vs[r * VS_STRIDE + c + 2] = tfr(v4.z);
            Vs[r * VS_STRIDE + c + 3] = tfr(v4.w);
        }
        __syncthreads();  // K/V (and Q on j=0) visible

        // S = Q @ K^T  (warp's 16 rows x 64 keys)
        float accS[8][4];
#pragma unroll
        for (int nf = 0; nf < 8; nf++)
#pragma unroll
            for (int q = 0; q < 4; q++) accS[nf][q] = 0.0f;

#pragma unroll
        for (int kk = 0; kk < 64; kk += 8) {
            unsigned a[4];
            int r = mb + (lane >> 2);
            int c = kk + (lane & 3);
            a[0] = __float_as_uint(Qs[r * QS_STRIDE + c]);
            a[1] = __float_as_uint(Qs[(r + 8) * QS_STRIDE + c]);
            a[2] = __float_as_uint(Qs[r * QS_STRIDE + c + 4]);
            a[3] = __float_as_uint(Qs[(r + 8) * QS_STRIDE + c + 4]);
#pragma unroll
            for (int nf = 0; nf < 8; nf++) {
                unsigned bf[2];
                int kr = nf * 8 + (lane >> 2);
                bf[0] = __float_as_uint(Ks[kr * QS_STRIDE + c]);
                bf[1] = __float_as_uint(Ks[kr * QS_STRIDE + c + 4]);
                mma8(accS[nf], a, bf);
            }
        }

        // Online softmax (2 rows per thread: r0=mb+lane/4, r1=r0+8)
        float tm0 = -1e30f, tm1 = -1e30f;
#pragma unroll
        for (int nf = 0; nf < 8; nf++) {
            tm0 = fmaxf(tm0, fmaxf(accS[nf][0], accS[nf][1]));
            tm1 = fmaxf(tm1, fmaxf(accS[nf][2], accS[nf][3]));
        }
        tm0 = fmaxf(tm0, __shfl_xor_sync(0xffffffffu, tm0, 1));
        tm0 = fmaxf(tm0, __shfl_xor_sync(0xffffffffu, tm0, 2));
        tm1 = fmaxf(tm1, __shfl_xor_sync(0xffffffffu, tm1, 1));
        tm1 = fmaxf(tm1, __shfl_xor_sync(0xffffffffu, tm1, 2));

        float mn0 = fmaxf(mrow[0], tm0), mn1 = fmaxf(mrow[1], tm1);
        float al0 = __expf(mrow[0] - mn0), al1 = __expf(mrow[1] - mn1);

        float s0 = 0.0f, s1 = 0.0f;
#pragma unroll
        for (int nf = 0; nf < 8; nf++) {
            accS[nf][0] = __expf(accS[nf][0] - mn0);
            accS[nf][1] = __expf(accS[nf][1] - mn0);
            accS[nf][2] = __expf(accS[nf][2] - mn1);
            accS[nf][3] = __expf(accS[nf][3] - mn1);
            s0 += accS[nf][0] + accS[nf][1];
            s1 += accS[nf][2] + accS[nf][3];
        }
        s0 += __shfl_xor_sync(0xffffffffu, s0, 1);
        s0 += __shfl_xor_sync(0xffffffffu, s0, 2);
        s1 += __shfl_xor_sync(0xffffffffu, s1, 1);
        s1 += __shfl_xor_sync(0xffffffffu, s1, 2);

        lrow[0] = lrow[0] * al0 + s0;
        lrow[1] = lrow[1] * al1 + s1;
        mrow[0] = mn0; mrow[1] = mn1;

#pragma unroll
        for (int nf = 0; nf < 8; nf++) {
            accO[nf][0] *= al0; accO[nf][1] *= al0;
            accO[nf][2] *= al1; accO[nf][3] *= al1;
        }

        // Store P (tf32-rounded) to warp-private rows of Ss
        {
            int r0 = mb + (lane >> 2);
#pragma unroll
            for (int nf = 0; nf < 8; nf++) {
                int c0 = nf * 8 + 2 * (lane & 3);
                Ss[r0 * QS_STRIDE + c0]           = tfr(accS[nf][0]);
                Ss[r0 * QS_STRIDE + c0 + 1]       = tfr(accS[nf][1]);
                Ss[(r0 + 8) * QS_STRIDE + c0]     = tfr(accS[nf][2]);
                Ss[(r0 + 8) * QS_STRIDE + c0 + 1] = tfr(accS[nf][3]);
            }
        }
        __syncwarp();  // warp-local P round-trip only

        // O += P @ V
#pragma unroll
        for (int kk = 0; kk < 64; kk += 8) {
            unsigned a[4];
            int r = mb + (lane >> 2);
            int c = kk + (lane & 3);
            a[0] = __float_as_uint(Ss[r * QS_STRIDE + c]);
            a[1] = __float_as_uint(Ss[(r + 8) * QS_STRIDE + c]);
            a[2] = __float_as_uint(Ss[r * QS_STRIDE + c + 4]);
            a[3] = __float_as_uint(Ss[(r + 8) * QS_STRIDE + c + 4]);
#pragma unroll
            for (int nf = 0; nf < 8; nf++) {
                unsigned bf[2];
                int vc = nf * 8 + (lane >> 2);
                bf[0] = __float_as_uint(Vs[(kk + (lane & 3)) * VS_STRIDE + vc]);
                bf[1] = __float_as_uint(Vs[(kk + (lane & 3) + 4) * VS_STRIDE + vc]);
                mma8(accO[nf], a, bf);
            }
        }
    }

    // Normalize and write to y in [B, T, C] layout
    float inv0 = 1.0f / lrow[0], inv1 = 1.0f / lrow[1];
    int r0 = mb + (lane >> 2);
    size_t t0 = (size_t)b * TS + (size_t)qt * 64 + r0;
#pragma unroll
    for (int nf = 0; nf < 8; nf++) {
        int c0 = nf * 8 + 2 * (lane & 3);
        float2 o0 = make_float2(accO[nf][0] * inv0, accO[nf][1] * inv0);
        *(float2*)(yg + t0 * DM + h * 64 + c0) = o0;
        float2 o1 = make_float2(accO[nf][2] * inv1, accO[nf][3] * inv1);
        *(float2*)(yg + (t0 + 8) * DM + h * 64 + c0) = o1;
    }
}

// ---------------------------------------------------------------------------
extern "C" void kernel_launch(void* const* d_in, const int* in_sizes, int n_in,
                              void* d_out, int out_size) {
    const float* x      = (const float*)d_in[0];
    const float* w_attn = (const float*)d_in[1];
    const float* b_attn = (const float*)d_in[2];
    const float* w_proj = (const float*)d_in[3];
    const float* b_proj = (const float*)d_in[4];
    float* out = (float*)d_out;

    float *qp, *kp, *vp, *yp;
    cudaGetSymbolAddress((void**)&qp, g_q);
    cudaGetSymbolAddress((void**)&kp, g_k);
    cudaGetSymbolAddress((void**)&vp, g_v);
    cudaGetSymbolAddress((void**)&yp, g_y);

    const int smem_attn = (3 * 64 * QS_STRIDE + 64 * VS_STRIDE) * 4;  // 76800 B
    cudaFuncSetAttribute(attn_kernel, cudaFuncAttributeMaxDynamicSharedMemorySize,
                         smem_attn);

    // 1) QKV projection + scatter to [B,H,T,dk] (Q pre-scaled)
    gemm_tn<1><<<dim3(3 * DM / 128, MTOT / 128), 256>>>(
        x, w_attn, b_attn, nullptr, qp, kp, vp, MTOT, 3 * DM, DM);

    // 2) Flash attention -> y [B,T,C]
    attn_kernel<<<dim3(TS / 64, NH, BB), 128, smem_attn>>>(qp, kp, vp, yp);

    // 3) Output projection -> d_out
    gemm_tn<0><<<dim3(DM / 128, MTOT / 128), 256>>>(
        yp, w_proj, b_proj, out, nullptr, nullptr, nullptr, MTOT, DM, DM);
}